// round 9
// baseline (speedup 1.0000x reference)
#include <cuda_runtime.h>

// MonteCarloPooling: per 2x2 block of x, Gumbel-max categorical sample using
// pre-drawn uniforms u; output = sampled index (0..3) as float.
//
// Equivalence chain:
//   argmax_k [ log(max(b_k,EPS)) - log(-log(clip(u_k))) ]
// = argmax_k [ max(b_k,EPS) / (-log(clip(u_k))) ]          (exp monotone)
// = cross-multiply champion compare (t_k > 0):
//     b_i/t_i > b_j/t_j  <=>  b_i*t_j > b_j*t_i
//
// R9: 8 outputs/thread (16x LDG.128 front batch) + __launch_bounds__(256, 3)
// (reg cap 85) so ptxas has the register budget to keep the batch intact.
// R8 proved the envelope mechanism (minBlocks=5 -> 48 regs -> 8-load batch,
// DRAM 87.8%); this scales it: 24 warps x 16 = 384 loads in flight vs 320.

#define MCP_EPS 1e-12f

// x: (32,64,224,224) fp32; u: (32,64,112,112,4) fp32; out: (32,64,112,112) fp32
static constexpr unsigned PW  = 112;      // pooled width
static constexpr unsigned PH  = 112;      // pooled height
static constexpr unsigned W   = 224;      // input width
static constexpr unsigned SPR = PW / 8;   // 14 8-output spans per pooled row

__device__ __forceinline__ float mcp_pick(float b0, float b1, float b2, float b3,
                                          float4 uu)
{
    // t_k = -log(max(u_k, EPS)) > 0 (accurate logf: argmax-flip budget)
    float t0 = -logf(fmaxf(uu.x, MCP_EPS));
    float t1 = -logf(fmaxf(uu.y, MCP_EPS));
    float t2 = -logf(fmaxf(uu.z, MCP_EPS));
    float t3 = -logf(fmaxf(uu.w, MCP_EPS));

    b0 = fmaxf(b0, MCP_EPS);
    b1 = fmaxf(b1, MCP_EPS);
    b2 = fmaxf(b2, MCP_EPS);
    b3 = fmaxf(b3, MCP_EPS);

    // first-occurrence argmax of b_k/t_k (strict >, jnp.argmax semantics)
    float bb = b0, bt = t0;
    int   idx = 0;
    if (b1 * bt > bb * t1) { bb = b1; bt = t1; idx = 1; }
    if (b2 * bt > bb * t2) { bb = b2; bt = t2; idx = 2; }
    if (b3 * bt > bb * t3) { idx = 3; }
    return (float)idx;
}

__global__ void __launch_bounds__(256, 3)
mcpool_kernel(const float* __restrict__ x,
              const float* __restrict__ u,
              float* __restrict__ out,
              unsigned n8)  // number of 8-output spans
{
    unsigned t = blockIdx.x * blockDim.x + threadIdx.x;
    if (t >= n8) return;

    // 32-bit decomposition, constant divisors -> magic multiplies
    unsigned s   = t % SPR;        // span within pooled row (0..13)
    unsigned row = t / SPR;        // bc*PH + h
    unsigned h   = row % PH;
    unsigned bc  = row / PH;       // fused batch*channel (0..2047)

    // ---- 16-wide LDG.128 front batch ----
    // x rows 2h and 2h+1, input cols [16s, 16s+16): 4 contiguous float4 each
    const float4* xr0 = (const float4*)(x + (bc * (2u * PH) + 2u * h) * W + 16u * s);
    const float4* xr1 = (const float4*)((const float*)xr0 + W);
    const float4* up  = (const float4*)u + (t * 8u);   // 32 contiguous floats

    float4 a0 = __ldcs(xr0 + 0);
    float4 a1 = __ldcs(xr0 + 1);
    float4 a2 = __ldcs(xr0 + 2);
    float4 a3 = __ldcs(xr0 + 3);
    float4 c0 = __ldcs(xr1 + 0);
    float4 c1 = __ldcs(xr1 + 1);
    float4 c2 = __ldcs(xr1 + 2);
    float4 c3 = __ldcs(xr1 + 3);
    float4 u0 = __ldcs(up + 0);
    float4 u1 = __ldcs(up + 1);
    float4 u2 = __ldcs(up + 2);
    float4 u3 = __ldcs(up + 3);
    float4 u4 = __ldcs(up + 4);
    float4 u5 = __ldcs(up + 5);
    float4 u6 = __ldcs(up + 6);
    float4 u7 = __ldcs(up + 7);

    // block flatten order k = 2*row_in_block + col_in_block
    float4 r0, r1;
    r0.x = mcp_pick(a0.x, a0.y, c0.x, c0.y, u0);
    r0.y = mcp_pick(a0.z, a0.w, c0.z, c0.w, u1);
    r0.z = mcp_pick(a1.x, a1.y, c1.x, c1.y, u2);
    r0.w = mcp_pick(a1.z, a1.w, c1.z, c1.w, u3);
    r1.x = mcp_pick(a2.x, a2.y, c2.x, c2.y, u4);
    r1.y = mcp_pick(a2.z, a2.w, c2.z, c2.w, u5);
    r1.z = mcp_pick(a3.x, a3.y, c3.x, c3.y, u6);
    r1.w = mcp_pick(a3.z, a3.w, c3.z, c3.w, u7);

    float4* op = (float4*)out + (t * 2u);
    __stcs(op + 0, r0);
    __stcs(op + 1, r1);
}

extern "C" void kernel_launch(void* const* d_in, const int* in_sizes, int n_in,
                              void* d_out, int out_size)
{
    const float* x = (const float*)d_in[0];
    const float* u = (const float*)d_in[1];
    float* out = (float*)d_out;

    unsigned n8 = (unsigned)(out_size / 8);   // 3,211,264 spans
    unsigned threads = 256;
    unsigned blocks = (n8 + threads - 1) / threads;
    mcpool_kernel<<<blocks, threads>>>(x, u, out, n8);
}

// round 10
// speedup vs baseline: 1.1046x; 1.1046x over previous
#include <cuda_runtime.h>

// MonteCarloPooling: per 2x2 block of x, Gumbel-max categorical sample using
// pre-drawn uniforms u; output = sampled index (0..3) as float.
//
// Equivalence chain:
//   argmax_k [ log(max(b_k,EPS)) - log(-log(clip(u_k))) ]
// = argmax_k [ max(b_k,EPS) / (-log(clip(u_k))) ]          (exp monotone)
// = cross-multiply champion compare (t_k > 0):
//     b_i/t_i > b_j/t_j  <=>  b_i*t_j > b_j*t_i
//
// R10: R8 champion shape (4 outputs/thread, launch_bounds(256,5) envelope,
// cross-multiply epilogue) with the 8x LDG.128 front batch replaced by
// 4x LDG.256 (ld.global.cs.v8.f32, sm_100a+): same bytes, same registers,
// half the LSU dispatch slots and L1tex queue entries. R9 showed L1tex
// wavefront pressure is the second ceiling (91.5% at 16 loads/thread).

#define MCP_EPS 1e-12f

// x: (32,64,224,224) fp32; u: (32,64,112,112,4) fp32; out: (32,64,112,112) fp32
static constexpr unsigned PW  = 112;      // pooled width
static constexpr unsigned PH  = 112;      // pooled height
static constexpr unsigned W   = 224;      // input width
static constexpr unsigned GPR = PW / 4;   // 28 float4-groups per pooled row

// 256-bit evict-streaming load (Blackwell sm_100a+; 32B-aligned address)
__device__ __forceinline__ void ldcs_v8(const float* p,
                                        float& v0, float& v1, float& v2, float& v3,
                                        float& v4, float& v5, float& v6, float& v7)
{
    asm volatile("ld.global.cs.v8.f32 {%0,%1,%2,%3,%4,%5,%6,%7}, [%8];"
                 : "=f"(v0), "=f"(v1), "=f"(v2), "=f"(v3),
                   "=f"(v4), "=f"(v5), "=f"(v6), "=f"(v7)
                 : "l"(p) : "memory");
}

__device__ __forceinline__ float mcp_pick(float b0, float b1, float b2, float b3,
                                          float u0, float u1, float u2, float u3)
{
    // t_k = -log(max(u_k, EPS)) > 0 (accurate logf: argmax-flip budget —
    // MUFU.LG2's absolute error near u->1 risks exceeding the 1e-3 threshold)
    float t0 = -logf(fmaxf(u0, MCP_EPS));
    float t1 = -logf(fmaxf(u1, MCP_EPS));
    float t2 = -logf(fmaxf(u2, MCP_EPS));
    float t3 = -logf(fmaxf(u3, MCP_EPS));

    b0 = fmaxf(b0, MCP_EPS);
    b1 = fmaxf(b1, MCP_EPS);
    b2 = fmaxf(b2, MCP_EPS);
    b3 = fmaxf(b3, MCP_EPS);

    // first-occurrence argmax of b_k/t_k (strict >, jnp.argmax semantics)
    float bb = b0, bt = t0;
    int   idx = 0;
    if (b1 * bt > bb * t1) { bb = b1; bt = t1; idx = 1; }
    if (b2 * bt > bb * t2) { bb = b2; bt = t2; idx = 2; }
    if (b3 * bt > bb * t3) { idx = 3; }
    return (float)idx;
}

__global__ void __launch_bounds__(256, 5)
mcpool_kernel(const float* __restrict__ x,
              const float* __restrict__ u,
              float* __restrict__ out,
              unsigned n4)  // number of 4-output groups
{
    unsigned t = blockIdx.x * blockDim.x + threadIdx.x;
    if (t >= n4) return;

    // 32-bit decomposition, constant divisors -> magic multiplies
    unsigned g   = t % GPR;        // float4-group within pooled row (0..27)
    unsigned row = t / GPR;        // bc*PH + h
    unsigned h   = row % PH;
    unsigned bc  = row / PH;       // fused batch*channel (0..2047)

    // ---- 4x LDG.256 front batch (same 32 floats as R8's 8x LDG.128) ----
    const float* xbase = x + (bc * (2u * PH) + 2u * h) * W + 8u * g;  // 32B-aligned
    const float* ubase = u + (t * 16u);                               // 64B-aligned

    float xt0,xt1,xt2,xt3,xt4,xt5,xt6,xt7;   // top row, cols 8g..8g+7
    float xb0,xb1,xb2,xb3,xb4,xb5,xb6,xb7;   // bottom row
    float q0,q1,q2,q3,q4,q5,q6,q7;           // u[0..7]
    float q8,q9,qa,qb,qc,qd,qe,qf;           // u[8..15]

    ldcs_v8(xbase,      xt0,xt1,xt2,xt3,xt4,xt5,xt6,xt7);
    ldcs_v8(xbase + W,  xb0,xb1,xb2,xb3,xb4,xb5,xb6,xb7);
    ldcs_v8(ubase,      q0,q1,q2,q3,q4,q5,q6,q7);
    ldcs_v8(ubase + 8,  q8,q9,qa,qb,qc,qd,qe,qf);

    // block flatten order k = 2*row_in_block + col_in_block
    float4 res;
    res.x = mcp_pick(xt0, xt1, xb0, xb1, q0, q1, q2, q3);
    res.y = mcp_pick(xt2, xt3, xb2, xb3, q4, q5, q6, q7);
    res.z = mcp_pick(xt4, xt5, xb4, xb5, q8, q9, qa, qb);
    res.w = mcp_pick(xt6, xt7, xb6, xb7, qc, qd, qe, qf);

    __stcs((float4*)out + t, res);
}

extern "C" void kernel_launch(void* const* d_in, const int* in_sizes, int n_in,
                              void* d_out, int out_size)
{
    const float* x = (const float*)d_in[0];
    const float* u = (const float*)d_in[1];
    float* out = (float*)d_out;

    unsigned n4 = (unsigned)(out_size / 4);   // 6,422,528 groups
    unsigned threads = 256;
    unsigned blocks = (n4 + threads - 1) / threads;
    mcpool_kernel<<<blocks, threads>>>(x, u, out, n4);
}

// round 11
// speedup vs baseline: 1.1148x; 1.0092x over previous
#include <cuda_runtime.h>

// MonteCarloPooling: per 2x2 block of x, Gumbel-max categorical sample using
// pre-drawn uniforms u; output = sampled index (0..3) as float.
//
// Equivalence chain:
//   argmax_k [ log(max(b_k,EPS)) - log(-log(clip(u_k))) ]
// = argmax_k [ max(b_k,EPS) / (-log(clip(u_k))) ]          (exp monotone)
// = cross-multiply champion compare (t_k > 0):
//     b_i/t_i > b_j/t_j  <=>  b_i*t_j > b_j*t_i
//
// FINAL (R8 champion, reverted after R9/R10 regressions):
//  - 4 outputs/thread, 8x LDG.128 front batch.
//  - __launch_bounds__(256, 5): reg envelope 51 -> ptxas lands at 48 regs and
//    its latency scheduler keeps the full 8-load batch (every tighter budget
//    made it interleave consumers and collapse MLP: R3/R4/R5/R7 evidence).
//  - Divide-free cross-multiply argmax (frees issue slots; issue 73%->57%).
//  - Accurate logf (MUFU.LG2's absolute error near u->1 would multiply
//    argmax flips ~100x; measured rel_err stays at 1.05e-4 << 1e-3).
//  - Measured 6957 GB/s = at the B300 path-independent LTS chip cap
//    (~6300 B/cyc); traffic (925 MB) is irreducible -> this is the floor.

#define MCP_EPS 1e-12f

// x: (32,64,224,224) fp32; u: (32,64,112,112,4) fp32; out: (32,64,112,112) fp32
static constexpr unsigned PW  = 112;      // pooled width
static constexpr unsigned PH  = 112;      // pooled height
static constexpr unsigned W   = 224;      // input width
static constexpr unsigned GPR = PW / 4;   // 28 float4-groups per pooled row

__device__ __forceinline__ float mcp_pick(float b0, float b1, float b2, float b3,
                                          float4 uu)
{
    // t_k = -log(max(u_k, EPS)) > 0
    float t0 = -logf(fmaxf(uu.x, MCP_EPS));
    float t1 = -logf(fmaxf(uu.y, MCP_EPS));
    float t2 = -logf(fmaxf(uu.z, MCP_EPS));
    float t3 = -logf(fmaxf(uu.w, MCP_EPS));

    b0 = fmaxf(b0, MCP_EPS);
    b1 = fmaxf(b1, MCP_EPS);
    b2 = fmaxf(b2, MCP_EPS);
    b3 = fmaxf(b3, MCP_EPS);

    // first-occurrence argmax of b_k/t_k (strict >, jnp.argmax semantics)
    float bb = b0, bt = t0;
    int   idx = 0;
    if (b1 * bt > bb * t1) { bb = b1; bt = t1; idx = 1; }
    if (b2 * bt > bb * t2) { bb = b2; bt = t2; idx = 2; }
    if (b3 * bt > bb * t3) { idx = 3; }
    return (float)idx;
}

__global__ void __launch_bounds__(256, 5)
mcpool_kernel(const float* __restrict__ x,
              const float* __restrict__ u,
              float* __restrict__ out,
              unsigned n4)  // number of 4-output groups
{
    unsigned t = blockIdx.x * blockDim.x + threadIdx.x;
    if (t >= n4) return;

    // 32-bit decomposition, constant divisors -> magic multiplies
    unsigned g   = t % GPR;        // float4-group within pooled row (0..27)
    unsigned row = t / GPR;        // bc*PH + h
    unsigned h   = row % PH;
    unsigned bc  = row / PH;       // fused batch*channel (0..2047)

    // ---- 8-wide LDG.128 front batch ----
    const float*  xbase = x + (bc * (2u * PH) + 2u * h) * W + 8u * g;
    const float4* xr0   = (const float4*)xbase;        // row 2h
    const float4* xr1   = (const float4*)(xbase + W);  // row 2h+1
    const float4* up    = (const float4*)u + (t * 4u);

    float4 a0 = __ldcs(xr0 + 0);   // top row, cols 8g..8g+3
    float4 a1 = __ldcs(xr0 + 1);   // top row, cols 8g+4..8g+7
    float4 c0 = __ldcs(xr1 + 0);   // bottom row
    float4 c1 = __ldcs(xr1 + 1);
    float4 u0 = __ldcs(up + 0);
    float4 u1 = __ldcs(up + 1);
    float4 u2 = __ldcs(up + 2);
    float4 u3 = __ldcs(up + 3);

    // block flatten order k = 2*row_in_block + col_in_block
    float4 res;
    res.x = mcp_pick(a0.x, a0.y, c0.x, c0.y, u0);
    res.y = mcp_pick(a0.z, a0.w, c0.z, c0.w, u1);
    res.z = mcp_pick(a1.x, a1.y, c1.x, c1.y, u2);
    res.w = mcp_pick(a1.z, a1.w, c1.z, c1.w, u3);

    __stcs((float4*)out + t, res);
}

extern "C" void kernel_launch(void* const* d_in, const int* in_sizes, int n_in,
                              void* d_out, int out_size)
{
    const float* x = (const float*)d_in[0];
    const float* u = (const float*)d_in[1];
    float* out = (float*)d_out;

    unsigned n4 = (unsigned)(out_size / 4);   // 6,422,528 groups
    unsigned threads = 256;
    unsigned blocks = (n4 + threads - 1) / threads;
    mcpool_kernel<<<blocks, threads>>>(x, u, out, n4);
}

// round 12
// speedup vs baseline: 1.1172x; 1.0022x over previous
#include <cuda_runtime.h>

// MonteCarloPooling: per 2x2 block of x, Gumbel-max categorical sample using
// pre-drawn uniforms u; output = sampled index (0..3) as float.
//
// Equivalence chain:
//   argmax_k [ log(max(b_k,EPS)) - log(-log(clip(u_k))) ]
// = argmax_k [ max(b_k,EPS) / (-log(clip(u_k))) ]          (exp monotone)
// = cross-multiply champion compare (t_k > 0):
//     b_i/t_i > b_j/t_j  <=>  b_i*t_j > b_j*t_i
//
// R12: R8 champion per-thread shape (4 outputs/thread, 8x LDG.128 front
// batch, 48 regs, cross-multiply argmax, accurate logf), re-packed as
// 192 threads x 7 CTAs/SM: 1344 threads = 42 warps/SM at reg cap
// floor(65536/1344)=48 — same register count ptxas chose naturally, so
// identical per-thread code, +5% resident warps -> 336 loads in flight
// vs 320. In-flight loads has been the dur-tracking metric in all 11 rounds.

#define MCP_EPS 1e-12f

// x: (32,64,224,224) fp32; u: (32,64,112,112,4) fp32; out: (32,64,112,112) fp32
static constexpr unsigned PW  = 112;      // pooled width
static constexpr unsigned PH  = 112;      // pooled height
static constexpr unsigned W   = 224;      // input width
static constexpr unsigned GPR = PW / 4;   // 28 float4-groups per pooled row

__device__ __forceinline__ float mcp_pick(float b0, float b1, float b2, float b3,
                                          float4 uu)
{
    // t_k = -log(max(u_k, EPS)) > 0 (accurate logf: argmax-flip budget —
    // MUFU.LG2's absolute error near u->1 would exceed the 1e-3 threshold)
    float t0 = -logf(fmaxf(uu.x, MCP_EPS));
    float t1 = -logf(fmaxf(uu.y, MCP_EPS));
    float t2 = -logf(fmaxf(uu.z, MCP_EPS));
    float t3 = -logf(fmaxf(uu.w, MCP_EPS));

    b0 = fmaxf(b0, MCP_EPS);
    b1 = fmaxf(b1, MCP_EPS);
    b2 = fmaxf(b2, MCP_EPS);
    b3 = fmaxf(b3, MCP_EPS);

    // first-occurrence argmax of b_k/t_k (strict >, jnp.argmax semantics)
    float bb = b0, bt = t0;
    int   idx = 0;
    if (b1 * bt > bb * t1) { bb = b1; bt = t1; idx = 1; }
    if (b2 * bt > bb * t2) { bb = b2; bt = t2; idx = 2; }
    if (b3 * bt > bb * t3) { idx = 3; }
    return (float)idx;
}

__global__ void __launch_bounds__(192, 7)
mcpool_kernel(const float* __restrict__ x,
              const float* __restrict__ u,
              float* __restrict__ out,
              unsigned n4)  // number of 4-output groups
{
    unsigned t = blockIdx.x * blockDim.x + threadIdx.x;
    if (t >= n4) return;

    // 32-bit decomposition, constant divisors -> magic multiplies
    unsigned g   = t % GPR;        // float4-group within pooled row (0..27)
    unsigned row = t / GPR;        // bc*PH + h
    unsigned h   = row % PH;
    unsigned bc  = row / PH;       // fused batch*channel (0..2047)

    // ---- 8-wide LDG.128 front batch ----
    const float*  xbase = x + (bc * (2u * PH) + 2u * h) * W + 8u * g;
    const float4* xr0   = (const float4*)xbase;        // row 2h
    const float4* xr1   = (const float4*)(xbase + W);  // row 2h+1
    const float4* up    = (const float4*)u + (t * 4u);

    float4 a0 = __ldcs(xr0 + 0);   // top row, cols 8g..8g+3
    float4 a1 = __ldcs(xr0 + 1);   // top row, cols 8g+4..8g+7
    float4 c0 = __ldcs(xr1 + 0);   // bottom row
    float4 c1 = __ldcs(xr1 + 1);
    float4 u0 = __ldcs(up + 0);
    float4 u1 = __ldcs(up + 1);
    float4 u2 = __ldcs(up + 2);
    float4 u3 = __ldcs(up + 3);

    // block flatten order k = 2*row_in_block + col_in_block
    float4 res;
    res.x = mcp_pick(a0.x, a0.y, c0.x, c0.y, u0);
    res.y = mcp_pick(a0.z, a0.w, c0.z, c0.w, u1);
    res.z = mcp_pick(a1.x, a1.y, c1.x, c1.y, u2);
    res.w = mcp_pick(a1.z, a1.w, c1.z, c1.w, u3);

    __stcs((float4*)out + t, res);
}

extern "C" void kernel_launch(void* const* d_in, const int* in_sizes, int n_in,
                              void* d_out, int out_size)
{
    const float* x = (const float*)d_in[0];
    const float* u = (const float*)d_in[1];
    float* out = (float*)d_out;

    unsigned n4 = (unsigned)(out_size / 4);   // 6,422,528 groups
    unsigned threads = 192;
    unsigned blocks = (n4 + threads - 1) / threads;
    mcpool_kernel<<<blocks, threads>>>(x, u, out, n4);
}